// round 2
// baseline (speedup 1.0000x reference)
#include <cuda_runtime.h>
#include <cstdint>

// Scatter-add edge_features [B, M, F] into out [B, N, N, F] at (b, i, j)
// given pair_indices [B, M, 2] (int32 OR int64 — detected at runtime).
// Dataset: B=32, M=4096, F=64, N=128.

static constexpr int N_ATOMS = 128;
static constexpr int F_DIM   = 64;

// Flag: 1 if pair_indices buffer is int64, 0 if int32. Set by probe_kernel.
__device__ int g_idx_is64;

// ---------------------------------------------------------------------------
// Probe: under int64 layout, odd 32-bit words are high halves of values <128
// (all zero). Under int32, odd words are random j-indices in [0,128).
// ---------------------------------------------------------------------------
__global__ void probe_kernel(const int* __restrict__ idx_words) {
    int all_zero = 1;
    #pragma unroll
    for (int k = 1; k < 64; k += 2) {
        all_zero &= (idx_words[k] == 0);
    }
    g_idx_is64 = all_zero;
}

// ---------------------------------------------------------------------------
// Zero-fill output (d_out is poisoned to 0xAA before timing).
// ---------------------------------------------------------------------------
__global__ void zero_kernel(float4* __restrict__ out, long long n4) {
    long long idx    = (long long)blockIdx.x * blockDim.x + threadIdx.x;
    long long stride = (long long)gridDim.x * blockDim.x;
    float4 z = make_float4(0.f, 0.f, 0.f, 0.f);
    for (; idx < n4; idx += stride) {
        out[idx] = z;
    }
}

// ---------------------------------------------------------------------------
// Scatter-add: 16 threads per edge, one float4 (4 of F=64 floats) each.
// red.global.add.v4.f32 — no-return reduction, avoids ATOMG round trip.
// ---------------------------------------------------------------------------
__global__ void scatter_kernel(const float4* __restrict__ edge_feat4,  // [B*M*16]
                               const void* __restrict__ pair_idx_raw,  // [B*M*2] i32 or i64
                               float* __restrict__ out,                // [B*N*N*F]
                               long long n_edges,                      // B*M
                               int m_per_batch)                        // M
{
    long long tid   = (long long)blockIdx.x * blockDim.x + threadIdx.x;
    long long total = n_edges * (F_DIM / 4);
    if (tid >= total) return;

    long long edge  = tid >> 4;         // / 16
    int       chunk = (int)(tid & 15);  // % 16

    int b = (int)(edge / m_per_batch);

    long long i, j;
    if (g_idx_is64) {
        const long long* p = (const long long*)pair_idx_raw;
        i = p[edge * 2 + 0];
        j = p[edge * 2 + 1];
    } else {
        const int* p = (const int*)pair_idx_raw;
        i = p[edge * 2 + 0];
        j = p[edge * 2 + 1];
    }

    // Safety: skip out-of-range rather than crash (turns a model error into a
    // diagnosable rel_err failure).
    if ((unsigned long long)i >= N_ATOMS || (unsigned long long)j >= N_ATOMS) return;

    float4 v = edge_feat4[(edge << 4) + chunk];

    long long dst = ((((long long)b * N_ATOMS + i) * N_ATOMS + j) * F_DIM)
                    + (long long)chunk * 4;
    float* dptr = out + dst;

    asm volatile("red.global.add.v4.f32 [%0], {%1, %2, %3, %4};"
                 :
                 : "l"(dptr), "f"(v.x), "f"(v.y), "f"(v.z), "f"(v.w)
                 : "memory");
}

// ---------------------------------------------------------------------------
// Launch
// ---------------------------------------------------------------------------
extern "C" void kernel_launch(void* const* d_in, const int* in_sizes, int n_in,
                              void* d_out, int out_size)
{
    const float* edge_features = (const float*)d_in[0];  // [B, M, F]
    const void*  pair_indices  = d_in[1];                // [B, M, 2]

    long long n_edges = (long long)in_sizes[1] / 2;                  // B*M
    int B = out_size / (N_ATOMS * N_ATOMS * F_DIM);                  // 32
    int M = (int)(n_edges / B);                                      // 4096

    float* out = (float*)d_out;

    // 0) detect index dtype
    probe_kernel<<<1, 1>>>((const int*)pair_indices);

    // 1) zero-fill
    long long n4 = (long long)out_size / 4;
    zero_kernel<<<2048, 256>>>((float4*)out, n4);

    // 2) scatter-add
    long long total = n_edges * (F_DIM / 4);
    int threads = 256;
    int blocks  = (int)((total + threads - 1) / threads);
    scatter_kernel<<<blocks, threads>>>((const float4*)edge_features,
                                        pair_indices, out,
                                        n_edges, M);
}

// round 3
// speedup vs baseline: 1.0989x; 1.0989x over previous
#include <cuda_runtime.h>
#include <cstdint>

// Scatter-add edge_features [B, M, F] into out [B, N, N, F] at (b, i, j)
// given pair_indices [B, M, 2] (int32 OR int64 — detected on device).
// Dataset: B=32, M=4096, F=64, N=128.

static constexpr int N_ATOMS = 128;
static constexpr int F_DIM   = 64;

// 1 if pair_indices buffer is int64, 0 if int32. Written by zero_probe_kernel
// (stream-ordered before scatter_kernel reads it).
__device__ int g_idx_is64;

// ---------------------------------------------------------------------------
// Kernel 1: zero-fill output + embedded dtype probe (block 0, warp 0).
// Probe: under int64 layout every odd 32-bit word is the high half of a value
// < 128 (all zero). Under int32 odd words are random j-indices in [0,128);
// P(32 consecutive zeros) ~ 128^-32.
// ---------------------------------------------------------------------------
__global__ void zero_probe_kernel(float4* __restrict__ out, long long n4,
                                  const int* __restrict__ idx_words) {
    if (blockIdx.x == 0 && threadIdx.x < 32) {
        int w = idx_words[threadIdx.x * 2 + 1];
        unsigned ball = __ballot_sync(0xffffffffu, w == 0);
        if (threadIdx.x == 0) g_idx_is64 = (ball == 0xffffffffu) ? 1 : 0;
    }

    long long idx    = (long long)blockIdx.x * blockDim.x + threadIdx.x;
    long long stride = (long long)gridDim.x * blockDim.x;
    float4 z = make_float4(0.f, 0.f, 0.f, 0.f);
    for (; idx < n4; idx += stride) {
        out[idx] = z;
    }
}

// ---------------------------------------------------------------------------
// Kernel 2: scatter-add. 16 threads per edge, one float4 (4 of F=64) each.
// red.global.add.v4.f32 — no-return reduction (REDG path, no round trip).
// ---------------------------------------------------------------------------
__global__ void scatter_kernel(const float4* __restrict__ edge_feat4,  // [B*M*16]
                               const void* __restrict__ pair_idx_raw,  // [B*M*2]
                               float* __restrict__ out,                // [B*N*N*F]
                               int n_edges,                            // B*M
                               int m_per_batch)                        // M
{
    int tid   = blockIdx.x * blockDim.x + threadIdx.x;
    int total = n_edges * (F_DIM / 4);
    if (tid >= total) return;

    int edge  = tid >> 4;
    int chunk = tid & 15;
    int b     = edge / m_per_batch;

    const int is64 = g_idx_is64;  // uniform branch

    unsigned i, j;
    if (is64) {
        const long long* p = (const long long*)pair_idx_raw;
        i = (unsigned)p[edge * 2 + 0];
        j = (unsigned)p[edge * 2 + 1];
    } else {
        const int* p = (const int*)pair_idx_raw;
        i = (unsigned)p[edge * 2 + 0];
        j = (unsigned)p[edge * 2 + 1];
    }

    // Skip out-of-range rather than crash (model error -> rel_err, not UB).
    if (i >= N_ATOMS || j >= N_ATOMS) return;

    float4 v = edge_feat4[(edge << 4) + chunk];

    // All offsets fit in 32 bits: max = 32*128*128*64 = 2^25 * something < 2^31.
    unsigned dst = ((((unsigned)b * N_ATOMS + i) * N_ATOMS + j) * F_DIM)
                   + (unsigned)chunk * 4;
    float* dptr = out + dst;

    asm volatile("red.global.add.v4.f32 [%0], {%1, %2, %3, %4};"
                 :
                 : "l"(dptr), "f"(v.x), "f"(v.y), "f"(v.z), "f"(v.w)
                 : "memory");
}

// ---------------------------------------------------------------------------
// Launch
// ---------------------------------------------------------------------------
extern "C" void kernel_launch(void* const* d_in, const int* in_sizes, int n_in,
                              void* d_out, int out_size)
{
    const float* edge_features = (const float*)d_in[0];  // [B, M, F]
    const void*  pair_indices  = d_in[1];                // [B, M, 2]

    int n_edges = in_sizes[1] / 2;                       // B*M = 131072
    int B = out_size / (N_ATOMS * N_ATOMS * F_DIM);      // 32
    int M = n_edges / B;                                 // 4096

    float* out = (float*)d_out;

    // 1) zero-fill + dtype probe
    long long n4 = (long long)out_size / 4;              // 8,388,608 float4
    {
        int threads = 512;
        int blocks  = 2960;  // ~148 SMs * 20 blocks -> grid-stride, short tail
        zero_probe_kernel<<<blocks, threads>>>((float4*)out, n4,
                                               (const int*)pair_indices);
    }

    // 2) scatter-add
    {
        int total   = n_edges * (F_DIM / 4);             // 2,097,152
        int threads = 256;
        int blocks  = (total + threads - 1) / threads;
        scatter_kernel<<<blocks, threads>>>((const float4*)edge_features,
                                            pair_indices, out,
                                            n_edges, M);
    }
}